// round 11
// baseline (speedup 1.0000x reference)
#include <cuda_runtime.h>
#include <cuda_fp16.h>
#include <cstdint>

typedef __half fp16;

// Problem constants
#define BATCH 2
#define SEQ   2048
#define EMB   1024
#define NH    16
#define HD    64
#define MTOT  (BATCH * SEQ)     // 4096
#define NQKV  (3 * EMB)         // 3072

// ---------------------------------------------------------------------------
// Device-global scratch (allocation-free rule)
// ---------------------------------------------------------------------------
__device__ fp16 g_xh[(size_t)MTOT * EMB],  g_xl[(size_t)MTOT * EMB];
__device__ fp16 g_wqh[(size_t)NQKV * EMB];                 // weights: hi only
__device__ fp16 g_woh[(size_t)EMB * EMB];
__device__ fp16 g_qh[(size_t)MTOT * EMB], g_ql[(size_t)MTOT * EMB];   // Q planes
__device__ fp16 g_kh[(size_t)MTOT * EMB];                  // K: hi only
__device__ fp16 g_vth[(size_t)BATCH * NH * HD * SEQ];      // V^T: hi only
__device__ fp16 g_ath[(size_t)MTOT * EMB], g_atl[(size_t)MTOT * EMB]; // attn out

// ---------------------------------------------------------------------------
// Helpers
// ---------------------------------------------------------------------------
__device__ __forceinline__ uint32_t smem_u32(const void* p) {
    uint32_t a;
    asm("{ .reg .u64 t; cvta.to.shared.u64 t, %1; cvt.u32.u64 %0, t; }"
        : "=r"(a) : "l"(p));
    return a;
}
// fp16 split: (x,y) -> hi pair (rounded), lo pair (residual)
__device__ __forceinline__ void packsplith(float x, float y,
                                           uint32_t& hi, uint32_t& lo) {
    __half2 h = __floats2half2_rn(x, y);
    float2 hf = __half22float2(h);
    __half2 l = __floats2half2_rn(x - hf.x, y - hf.y);
    hi = *reinterpret_cast<uint32_t*>(&h);
    lo = *reinterpret_cast<uint32_t*>(&l);
}
__device__ __forceinline__ uint32_t packh(float x, float y) {
    __half2 h = __floats2half2_rn(x, y);
    return *reinterpret_cast<uint32_t*>(&h);
}

// fp16 inputs, fp32 accum
__device__ __forceinline__ void mmaf32(float* d, const uint32_t* a,
                                       const uint32_t* b) {
    asm volatile(
        "mma.sync.aligned.m16n8k16.row.col.f32.f16.f16.f32 "
        "{%0,%1,%2,%3}, {%4,%5,%6,%7}, {%8,%9}, {%0,%1,%2,%3};"
        : "+f"(d[0]), "+f"(d[1]), "+f"(d[2]), "+f"(d[3])
        : "r"(a[0]), "r"(a[1]), "r"(a[2]), "r"(a[3]), "r"(b[0]), "r"(b[1]));
}
__device__ __forceinline__ void ldm_x4(uint32_t* r, uint32_t addr) {
    asm volatile("ldmatrix.sync.aligned.m8n8.x4.shared.b16 {%0,%1,%2,%3}, [%4];"
                 : "=r"(r[0]), "=r"(r[1]), "=r"(r[2]), "=r"(r[3]) : "r"(addr));
}
__device__ __forceinline__ void ldm_x2(uint32_t* r, uint32_t addr) {
    asm volatile("ldmatrix.sync.aligned.m8n8.x2.shared.b16 {%0,%1}, [%2];"
                 : "=r"(r[0]), "=r"(r[1]) : "r"(addr));
}
__device__ __forceinline__ void cpa16(uint32_t dst, const void* src) {
    asm volatile("cp.async.cg.shared.global [%0], [%1], 16;" :: "r"(dst), "l"(src));
}
__device__ __forceinline__ void cp_commit() {
    asm volatile("cp.async.commit_group;" ::: "memory");
}
template <int N>
__device__ __forceinline__ void cp_wait() {
    asm volatile("cp.async.wait_group %0;" :: "n"(N) : "memory");
}

// ---------------------------------------------------------------------------
// Pre-convert kernels
// ---------------------------------------------------------------------------
__global__ void convert_split(const float4* __restrict__ in,
                              uint2* __restrict__ hi, uint2* __restrict__ lo,
                              int n4)
{
    int i = blockIdx.x * blockDim.x + threadIdx.x;
    if (i >= n4) return;
    float4 v = in[i];
    uint32_t h0, l0, h1, l1;
    packsplith(v.x, v.y, h0, l0);
    packsplith(v.z, v.w, h1, l1);
    hi[i] = make_uint2(h0, h1);
    lo[i] = make_uint2(l0, l1);
}
__global__ void convert_hi(const float4* __restrict__ in,
                           uint2* __restrict__ hi, int n4)
{
    int i = blockIdx.x * blockDim.x + threadIdx.x;
    if (i >= n4) return;
    float4 v = in[i];
    hi[i] = make_uint2(packh(v.x, v.y), packh(v.z, v.w));
}

// ---------------------------------------------------------------------------
// 2-term fp16 GEMM: C[M,N] = (Ah+Al)[M,K] @ Wh[N,K]^T + bias[N]
// CTA 128x128, BK=32, 8 warps (2m x 4n, warp tile 64x32), 3-stage cp.async ring.
// MODE 0: fp32 C out.  MODE 1: QKV out (Q hi/lo, K hi, V^T hi).
// ---------------------------------------------------------------------------
#define GBM 128
#define GBN 128
#define GBK 32
#define GA_LO  10240u
#define GB_HI  20480u
#define GSTAGE 30720u
#define GEMM_SMEM (3u * GSTAGE)   // 92160 bytes

template <int MODE>
__global__ __launch_bounds__(256, 1)
void gemm_2t(const fp16* __restrict__ Ah, const fp16* __restrict__ Al,
             const fp16* __restrict__ Bh,
             const float* __restrict__ bias, float* __restrict__ C,
             fp16* __restrict__ qh, fp16* __restrict__ ql,
             fp16* __restrict__ kh, fp16* __restrict__ vth,
             int M, int N, int K)
{
    extern __shared__ __align__(16) char sm[];
    const uint32_t sb = smem_u32(sm);
    const int tid = threadIdx.x;
    const int wid = tid >> 5, lane = tid & 31;
    const int g = lane >> 2, tg = lane & 3;
    const int m0 = blockIdx.y * GBM, n0 = blockIdx.x * GBN;
    const int m0w = (wid >> 2) * 64, n0w = (wid & 3) * 32;

    float acc[4][4][4];
#pragma unroll
    for (int i = 0; i < 4; i++)
#pragma unroll
        for (int j = 0; j < 4; j++)
#pragma unroll
            for (int e = 0; e < 4; e++) acc[i][j][e] = 0.0f;

    auto load_stage = [&](int c) {
        const int kt = c * GBK;
        const uint32_t so = (uint32_t)(c % 3) * GSTAGE;
#pragma unroll
        for (int i = 0; i < 4; i++) {                 // A hi+lo: 1024 16B chunks
            int ci = tid + i * 256;
            int row = ci >> 3, sub = ci & 7;
            int pl = sub >> 2, kc = sub & 3;
            const fp16* src = (pl ? Al : Ah) + (size_t)(m0 + row) * K + kt + kc * 8;
            cpa16(sb + so + (pl ? GA_LO : 0u) + (uint32_t)(row * 80 + kc * 16), src);
        }
#pragma unroll
        for (int i = 0; i < 2; i++) {                 // B hi: 512 16B chunks
            int ci = tid + i * 256;
            int row = ci >> 2, kc = ci & 3;
            const fp16* src = Bh + (size_t)(n0 + row) * K + kt + kc * 8;
            cpa16(sb + so + GB_HI + (uint32_t)(row * 80 + kc * 16), src);
        }
        cp_commit();
    };

    auto compute = [&](int c) {
        const uint32_t so = (uint32_t)(c % 3) * GSTAGE;
#pragma unroll
        for (int ks = 0; ks < 2; ks++) {
            const uint32_t kb = (uint32_t)(ks * 32);
            uint32_t aH[4][4], aL[4][4];
#pragma unroll
            for (int mf = 0; mf < 4; mf++) {
                uint32_t ad = sb + so +
                    (uint32_t)((m0w + mf * 16 + (lane & 15)) * 80) +
                    kb + (uint32_t)((lane >> 4) * 16);
                ldm_x4(aH[mf], ad);
                ldm_x4(aL[mf], ad + GA_LO);
            }
#pragma unroll
            for (int nf = 0; nf < 4; nf++) {
                uint32_t bd = sb + so + GB_HI +
                    (uint32_t)((n0w + nf * 8 + (lane & 7)) * 80) +
                    kb + (uint32_t)(((lane >> 3) & 1) * 16);
                uint32_t bH[2];
                ldm_x2(bH, bd);
#pragma unroll
                for (int mf = 0; mf < 4; mf++) {
                    mmaf32(acc[mf][nf], aH[mf], bH);
                    mmaf32(acc[mf][nf], aL[mf], bH);
                }
            }
        }
    };

    const int NC = K / GBK;
    load_stage(0);
    load_stage(1);
    for (int c = 0; c < NC; c++) {
        if (c == NC - 1) cp_wait<0>(); else cp_wait<1>();
        __syncthreads();
        if (c + 2 < NC) load_stage(c + 2);
        compute(c);
    }

    // ---- epilogue ----
#pragma unroll
    for (int mf = 0; mf < 4; mf++) {
        const int r = m0 + m0w + mf * 16 + g;
#pragma unroll
        for (int nf = 0; nf < 4; nf++) {
            const int col = n0 + n0w + nf * 8 + tg * 2;
            const float b0 = bias[col], b1 = bias[col + 1];
#pragma unroll
            for (int half = 0; half < 2; half++) {
                const int rr = r + half * 8;
                const float v0 = acc[mf][nf][half * 2 + 0] + b0;
                const float v1 = acc[mf][nf][half * 2 + 1] + b1;
                if (MODE == 0) {
                    *(float2*)(C + (size_t)rr * N + col) = make_float2(v0, v1);
                } else {
                    if (col < 1024) {                 // Q: hi + lo planes
                        uint32_t hi, lo;
                        packsplith(v0, v1, hi, lo);
                        *(uint32_t*)(qh + (size_t)rr * EMB + col) = hi;
                        *(uint32_t*)(ql + (size_t)rr * EMB + col) = lo;
                    } else if (col < 2048) {          // K: hi only
                        *(uint32_t*)(kh + (size_t)rr * EMB + (col - 1024)) =
                            packh(v0, v1);
                    } else {                          // V: transposed, hi only
                        const int d = col - 2048;
                        const int hh = d >> 6, dd = d & 63;
                        const int bb = rr >> 11, rs = rr & 2047;
                        const size_t vb =
                            ((size_t)(bb * NH + hh) * HD + dd) * SEQ + rs;
                        vth[vb]       = __float2half_rn(v0);
                        vth[vb + SEQ] = __float2half_rn(v1);
                    }
                }
            }
        }
    }
}

// ---------------------------------------------------------------------------
// Flash attention, 2-term fp16 (Q,P split; K,V single-plane), double-buffered KV.
// CTA = 128 q rows x (b,h); 8 warps x 16 q rows; KV tiles of 128.
// smem: Q hi/lo 36.9KB + 2 KV stages (K 18.4KB + V 17.4KB each) = 108.5KB.
// ---------------------------------------------------------------------------
#define AQ_LO   18432u
#define AKV0    36864u
#define AKV_V   18432u   // within stage
#define AKVSTG  35840u
#define ATT_SMEM (AKV0 + 2u * AKVSTG)   // 108544 bytes

__global__ __launch_bounds__(256, 1)
void attention_mma(const fp16* __restrict__ qh, const fp16* __restrict__ ql,
                   const fp16* __restrict__ kh, const fp16* __restrict__ vth,
                   fp16* __restrict__ ath, fp16* __restrict__ atl,
                   const int* __restrict__ causal_flag)
{
    extern __shared__ __align__(16) char sm[];
    const uint32_t sb = smem_u32(sm);
    const int tid = threadIdx.x, wid = tid >> 5, lane = tid & 31;
    const int g = lane >> 2, tg = lane & 3;
    const int qt = (SEQ / 128 - 1) - blockIdx.x;   // long CTAs first
    const int bh = blockIdx.y, b = bh / NH, h = bh % NH;
    const int causal = *causal_flag;
    const int q0 = qt * 128;

    auto load_kv = [&](int kvt, int st) {
        const int kv0 = kvt * 128;
        const uint32_t so = AKV0 + (uint32_t)st * AKVSTG;
#pragma unroll
        for (int i = 0; i < 4; i++) {            // K hi: 1024 chunks
            int ci = tid + i * 256;
            int row = ci >> 3, kc = ci & 7;
            const fp16* src = kh + (size_t)(b * SEQ + kv0 + row) * EMB +
                              h * HD + kc * 8;
            cpa16(sb + so + (uint32_t)(row * 144 + kc * 16), src);
        }
#pragma unroll
        for (int i = 0; i < 4; i++) {            // V hi: 1024 chunks
            int ci = tid + i * 256;
            int row = ci >> 4, kc = ci & 15;
            const fp16* src = vth + ((size_t)bh * HD + row) * SEQ + kv0 + kc * 8;
            cpa16(sb + so + AKV_V + (uint32_t)(row * 272 + kc * 16), src);
        }
        cp_commit();
    };

    // ---- prologue: Q hi/lo + KV(0) ----
#pragma unroll
    for (int i = 0; i < 8; i++) {
        int ci = tid + i * 256;
        int row = ci >> 4, sub = ci & 15;
        int pl = sub >> 3, kc = sub & 7;
        const fp16* src = (pl ? ql : qh) +
            (size_t)(b * SEQ + q0 + row) * EMB + h * HD + kc * 8;
        cpa16(sb + (pl ? AQ_LO : 0u) + (uint32_t)(row * 144 + kc * 16), src);
    }
    load_kv(0, 0);

    float o[8][4];
#pragma unroll
    for (int i = 0; i < 8; i++)
#pragma unroll
        for (int e = 0; e < 4; e++) o[i][e] = 0.0f;
    float m0v = -1e30f, m1v = -1e30f, l0v = 0.0f, l1v = 0.0f;

    const int nkv = causal ? (qt + 1) : (SEQ / 128);
    for (int kvt = 0; kvt < nkv; kvt++) {
        cp_wait<0>();
        __syncthreads();
        if (kvt + 1 < nkv) load_kv(kvt + 1, (kvt + 1) & 1);  // overlaps compute

        const uint32_t kvb = AKV0 + (uint32_t)(kvt & 1) * AKVSTG;

        // ---- S = (Qh+Ql) @ Kh^T ----
        float s[16][4];
#pragma unroll
        for (int nf = 0; nf < 16; nf++)
#pragma unroll
            for (int e = 0; e < 4; e++) s[nf][e] = 0.0f;

#pragma unroll
        for (int ks = 0; ks < 4; ks++) {
            const uint32_t kb = (uint32_t)(ks * 32);
            uint32_t aH[4], aL[4];
            uint32_t ad = sb + (uint32_t)((wid * 16 + (lane & 15)) * 144) +
                          kb + (uint32_t)((lane >> 4) * 16);
            ldm_x4(aH, ad);
            ldm_x4(aL, ad + AQ_LO);
#pragma unroll
            for (int nf = 0; nf < 16; nf++) {
                uint32_t bd = sb + kvb +
                    (uint32_t)((nf * 8 + (lane & 7)) * 144) +
                    kb + (uint32_t)(((lane >> 3) & 1) * 16);
                uint32_t bH[2];
                ldm_x2(bH, bd);
                mmaf32(s[nf], aH, bH);
                mmaf32(s[nf], aL, bH);
            }
        }

        // ---- scale + causal mask (diagonal tile only) ----
        const bool dm = (causal != 0) && (kvt == qt);
#pragma unroll
        for (int nf = 0; nf < 16; nf++) {
#pragma unroll
            for (int e = 0; e < 4; e++) {
                float v = s[nf][e] * 0.125f;   // 1/sqrt(64)
                if (dm) {
                    int qr = wid * 16 + g + ((e >= 2) ? 8 : 0);
                    int kc = nf * 8 + tg * 2 + (e & 1);
                    if (kc > qr) v = -1e30f;
                }
                s[nf][e] = v;
            }
        }

        // ---- online softmax (rows g and g+8) ----
        float mx0 = -1e30f, mx1 = -1e30f;
#pragma unroll
        for (int nf = 0; nf < 16; nf++) {
            mx0 = fmaxf(mx0, fmaxf(s[nf][0], s[nf][1]));
            mx1 = fmaxf(mx1, fmaxf(s[nf][2], s[nf][3]));
        }
        mx0 = fmaxf(mx0, __shfl_xor_sync(0xffffffffu, mx0, 1));
        mx0 = fmaxf(mx0, __shfl_xor_sync(0xffffffffu, mx0, 2));
        mx1 = fmaxf(mx1, __shfl_xor_sync(0xffffffffu, mx1, 1));
        mx1 = fmaxf(mx1, __shfl_xor_sync(0xffffffffu, mx1, 2));

        const float mn0 = fmaxf(m0v, mx0), mn1 = fmaxf(m1v, mx1);
        const float al0 = __expf(m0v - mn0), al1 = __expf(m1v - mn1);
        m0v = mn0; m1v = mn1;

        float rs0 = 0.0f, rs1 = 0.0f;
#pragma unroll
        for (int nf = 0; nf < 16; nf++) {
            s[nf][0] = __expf(s[nf][0] - mn0); rs0 += s[nf][0];
            s[nf][1] = __expf(s[nf][1] - mn0); rs0 += s[nf][1];
            s[nf][2] = __expf(s[nf][2] - mn1); rs1 += s[nf][2];
            s[nf][3] = __expf(s[nf][3] - mn1); rs1 += s[nf][3];
        }
        rs0 += __shfl_xor_sync(0xffffffffu, rs0, 1);
        rs0 += __shfl_xor_sync(0xffffffffu, rs0, 2);
        rs1 += __shfl_xor_sync(0xffffffffu, rs1, 1);
        rs1 += __shfl_xor_sync(0xffffffffu, rs1, 2);
        l0v = l0v * al0 + rs0;
        l1v = l1v * al1 + rs1;

#pragma unroll
        for (int nf = 0; nf < 8; nf++) {
            o[nf][0] *= al0; o[nf][1] *= al0;
            o[nf][2] *= al1; o[nf][3] *= al1;
        }

        // ---- O += (Ph+Pl) @ Vh (P split in regs; V^T frags via ldmatrix) ----
#pragma unroll
        for (int kf = 0; kf < 8; kf++) {
            uint32_t aH[4], aL[4];
            packsplith(s[2 * kf][0],     s[2 * kf][1],     aH[0], aL[0]);
            packsplith(s[2 * kf][2],     s[2 * kf][3],     aH[1], aL[1]);
            packsplith(s[2 * kf + 1][0], s[2 * kf + 1][1], aH[2], aL[2]);
            packsplith(s[2 * kf + 1][2], s[2 * kf + 1][3], aH[3], aL[3]);
#pragma unroll
            for (int nf = 0; nf < 8; nf++) {
                uint32_t vd = sb + kvb + AKV_V +
                    (uint32_t)((nf * 8 + (lane & 7)) * 272) +
                    (uint32_t)(kf * 32) + (uint32_t)(((lane >> 3) & 1) * 16);
                uint32_t bH[2];
                ldm_x2(bH, vd);
                mmaf32(o[nf], aH, bH);
                mmaf32(o[nf], aL, bH);
            }
        }
        __syncthreads();   // all warps done with stage before next overwrite
    }

    // ---- normalize + write hi/lo fp16 planes of O ----
    const float inv0 = 1.0f / l0v, inv1 = 1.0f / l1v;
    const size_t r0 = (size_t)(b * SEQ + q0 + wid * 16 + g);
#pragma unroll
    for (int nf = 0; nf < 8; nf++) {
        const int col = h * HD + nf * 8 + tg * 2;
        uint32_t hi, lo;
        packsplith(o[nf][0] * inv0, o[nf][1] * inv0, hi, lo);
        *(uint32_t*)(ath + r0 * EMB + col) = hi;
        *(uint32_t*)(atl + r0 * EMB + col) = lo;
        packsplith(o[nf][2] * inv1, o[nf][3] * inv1, hi, lo);
        *(uint32_t*)(ath + (r0 + 8) * EMB + col) = hi;
        *(uint32_t*)(atl + (r0 + 8) * EMB + col) = lo;
    }
}

// ---------------------------------------------------------------------------
extern "C" void kernel_launch(void* const* d_in, const int* in_sizes, int n_in,
                              void* d_out, int out_size)
{
    (void)in_sizes; (void)n_in; (void)out_size;
    const float* x      = (const float*)d_in[0];
    const float* w_qkv  = (const float*)d_in[1];
    const float* b_qkv  = (const float*)d_in[2];
    const float* w_out  = (const float*)d_in[3];
    const float* b_out  = (const float*)d_in[4];
    const int*   causal = (const int*)d_in[5];
    float* out = (float*)d_out;

    fp16 *xh, *xl, *wqh, *woh, *qh, *ql, *kh, *vth, *ath, *atl;
    cudaGetSymbolAddress((void**)&xh,  g_xh);   cudaGetSymbolAddress((void**)&xl,  g_xl);
    cudaGetSymbolAddress((void**)&wqh, g_wqh);  cudaGetSymbolAddress((void**)&woh, g_woh);
    cudaGetSymbolAddress((void**)&qh,  g_qh);   cudaGetSymbolAddress((void**)&ql,  g_ql);
    cudaGetSymbolAddress((void**)&kh,  g_kh);   cudaGetSymbolAddress((void**)&vth, g_vth);
    cudaGetSymbolAddress((void**)&ath, g_ath);  cudaGetSymbolAddress((void**)&atl, g_atl);

    cudaFuncSetAttribute(gemm_2t<0>, cudaFuncAttributeMaxDynamicSharedMemorySize,
                         (int)GEMM_SMEM);
    cudaFuncSetAttribute(gemm_2t<1>, cudaFuncAttributeMaxDynamicSharedMemorySize,
                         (int)GEMM_SMEM);
    cudaFuncSetAttribute(attention_mma, cudaFuncAttributeMaxDynamicSharedMemorySize,
                         (int)ATT_SMEM);

    // 1) pre-convert: x -> hi/lo planes; weights -> hi plane only
    convert_split<<<(MTOT * EMB / 4 + 255) / 256, 256>>>(
        (const float4*)x, (uint2*)xh, (uint2*)xl, MTOT * EMB / 4);
    convert_hi<<<(NQKV * EMB / 4 + 255) / 256, 256>>>(
        (const float4*)w_qkv, (uint2*)wqh, NQKV * EMB / 4);
    convert_hi<<<(EMB * EMB / 4 + 255) / 256, 256>>>(
        (const float4*)w_out, (uint2*)woh, EMB * EMB / 4);

    // 2) QKV projection -> Q hi/lo, K hi, V^T hi
    gemm_2t<1><<<dim3(NQKV / GBN, MTOT / GBM), 256, GEMM_SMEM>>>(
        xh, xl, wqh, b_qkv, nullptr, qh, ql, kh, vth, MTOT, NQKV, EMB);

    // 3) causal flash attention -> O hi/lo planes
    attention_mma<<<dim3(SEQ / 128, BATCH * NH), 256, ATT_SMEM>>>(
        qh, ql, kh, vth, ath, atl, causal);

    // 4) output projection -> fp32 out
    gemm_2t<0><<<dim3(EMB / GBN, MTOT / GBM), 256, GEMM_SMEM>>>(
        ath, atl, woh, b_out, out, nullptr, nullptr, nullptr, nullptr,
        MTOT, EMB, EMB);
}

// round 12
// speedup vs baseline: 1.1112x; 1.1112x over previous
#include <cuda_runtime.h>
#include <cuda_fp16.h>
#include <cstdint>

typedef __half fp16;

// Problem constants
#define BATCH 2
#define SEQ   2048
#define EMB   1024
#define NH    16
#define HD    64
#define MTOT  (BATCH * SEQ)     // 4096
#define NQKV  (3 * EMB)         // 3072

// ---------------------------------------------------------------------------
// Device-global scratch (allocation-free rule)
// ---------------------------------------------------------------------------
__device__ fp16 g_xh[(size_t)MTOT * EMB],  g_xl[(size_t)MTOT * EMB];
__device__ fp16 g_wqh[(size_t)NQKV * EMB];                 // weights: hi only
__device__ fp16 g_woh[(size_t)EMB * EMB];
__device__ fp16 g_qh[(size_t)MTOT * EMB], g_ql[(size_t)MTOT * EMB];   // Q planes
__device__ fp16 g_kh[(size_t)MTOT * EMB];                  // K: hi only
__device__ fp16 g_vth[(size_t)BATCH * NH * HD * SEQ];      // V^T: hi only
__device__ fp16 g_ath[(size_t)MTOT * EMB], g_atl[(size_t)MTOT * EMB]; // attn out

// ---------------------------------------------------------------------------
// Helpers
// ---------------------------------------------------------------------------
__device__ __forceinline__ uint32_t smem_u32(const void* p) {
    uint32_t a;
    asm("{ .reg .u64 t; cvta.to.shared.u64 t, %1; cvt.u32.u64 %0, t; }"
        : "=r"(a) : "l"(p));
    return a;
}
// fp16 split: (x,y) -> hi pair (rounded), lo pair (residual)
__device__ __forceinline__ void packsplith(float x, float y,
                                           uint32_t& hi, uint32_t& lo) {
    __half2 h = __floats2half2_rn(x, y);
    float2 hf = __half22float2(h);
    __half2 l = __floats2half2_rn(x - hf.x, y - hf.y);
    hi = *reinterpret_cast<uint32_t*>(&h);
    lo = *reinterpret_cast<uint32_t*>(&l);
}
__device__ __forceinline__ uint32_t packh(float x, float y) {
    __half2 h = __floats2half2_rn(x, y);
    return *reinterpret_cast<uint32_t*>(&h);
}

// fp16 inputs, fp32 accum
__device__ __forceinline__ void mmaf32(float* d, const uint32_t* a,
                                       const uint32_t* b) {
    asm volatile(
        "mma.sync.aligned.m16n8k16.row.col.f32.f16.f16.f32 "
        "{%0,%1,%2,%3}, {%4,%5,%6,%7}, {%8,%9}, {%0,%1,%2,%3};"
        : "+f"(d[0]), "+f"(d[1]), "+f"(d[2]), "+f"(d[3])
        : "r"(a[0]), "r"(a[1]), "r"(a[2]), "r"(a[3]), "r"(b[0]), "r"(b[1]));
}
__device__ __forceinline__ void ldm_x4(uint32_t* r, uint32_t addr) {
    asm volatile("ldmatrix.sync.aligned.m8n8.x4.shared.b16 {%0,%1,%2,%3}, [%4];"
                 : "=r"(r[0]), "=r"(r[1]), "=r"(r[2]), "=r"(r[3]) : "r"(addr));
}
__device__ __forceinline__ void ldm_x2(uint32_t* r, uint32_t addr) {
    asm volatile("ldmatrix.sync.aligned.m8n8.x2.shared.b16 {%0,%1}, [%2];"
                 : "=r"(r[0]), "=r"(r[1]) : "r"(addr));
}
__device__ __forceinline__ void cpa16(uint32_t dst, const void* src) {
    asm volatile("cp.async.cg.shared.global [%0], [%1], 16;" :: "r"(dst), "l"(src));
}
__device__ __forceinline__ void cp_commit() {
    asm volatile("cp.async.commit_group;" ::: "memory");
}
template <int N>
__device__ __forceinline__ void cp_wait() {
    asm volatile("cp.async.wait_group %0;" :: "n"(N) : "memory");
}

// ---------------------------------------------------------------------------
// Pre-convert kernels
// ---------------------------------------------------------------------------
__global__ void convert_split(const float4* __restrict__ in,
                              uint2* __restrict__ hi, uint2* __restrict__ lo,
                              int n4)
{
    int i = blockIdx.x * blockDim.x + threadIdx.x;
    if (i >= n4) return;
    float4 v = in[i];
    uint32_t h0, l0, h1, l1;
    packsplith(v.x, v.y, h0, l0);
    packsplith(v.z, v.w, h1, l1);
    hi[i] = make_uint2(h0, h1);
    lo[i] = make_uint2(l0, l1);
}
__global__ void convert_hi(const float4* __restrict__ in,
                           uint2* __restrict__ hi, int n4)
{
    int i = blockIdx.x * blockDim.x + threadIdx.x;
    if (i >= n4) return;
    float4 v = in[i];
    hi[i] = make_uint2(packh(v.x, v.y), packh(v.z, v.w));
}

// ---------------------------------------------------------------------------
// fp16 GEMM: C[M,N] = A[M,K] @ Wh[N,K]^T + bias[N]
// A = Ah (+ Al where precision needed). CTA 128x128, BK=32, 8 warps, 3-stage ring.
// MODE 0: fp32 C out, A always 2-term.
// MODE 1: QKV out; A 2-term for Q columns (n0<1024), 1-term for K/V columns.
// ---------------------------------------------------------------------------
#define GBM 128
#define GBN 128
#define GBK 32
#define GA_LO  10240u
#define GB_HI  20480u
#define GSTAGE 30720u
#define GEMM_SMEM (3u * GSTAGE)   // 92160 bytes

template <int MODE>
__global__ __launch_bounds__(256, 1)
void gemm_2t(const fp16* __restrict__ Ah, const fp16* __restrict__ Al,
             const fp16* __restrict__ Bh,
             const float* __restrict__ bias, float* __restrict__ C,
             fp16* __restrict__ qh, fp16* __restrict__ ql,
             fp16* __restrict__ kh, fp16* __restrict__ vth,
             int M, int N, int K)
{
    extern __shared__ __align__(16) char sm[];
    const uint32_t sb = smem_u32(sm);
    const int tid = threadIdx.x;
    const int wid = tid >> 5, lane = tid & 31;
    const int g = lane >> 2, tg = lane & 3;
    const int m0 = blockIdx.y * GBM, n0 = blockIdx.x * GBN;
    const int m0w = (wid >> 2) * 64, n0w = (wid & 3) * 32;
    const bool needLo = (MODE == 0) || (n0 < 1024);   // Q cols: 2-term A

    float acc[4][4][4];
#pragma unroll
    for (int i = 0; i < 4; i++)
#pragma unroll
        for (int j = 0; j < 4; j++)
#pragma unroll
            for (int e = 0; e < 4; e++) acc[i][j][e] = 0.0f;

    auto load_stage = [&](int c) {
        const int kt = c * GBK;
        const uint32_t so = (uint32_t)(c % 3) * GSTAGE;
#pragma unroll
        for (int i = 0; i < 2; i++) {                 // A hi: 512 16B chunks
            int ci = tid + i * 256;
            int row = ci >> 2, kc = ci & 3;
            cpa16(sb + so + (uint32_t)(row * 80 + kc * 16),
                  Ah + (size_t)(m0 + row) * K + kt + kc * 8);
        }
        if (needLo) {
#pragma unroll
            for (int i = 0; i < 2; i++) {             // A lo: 512 16B chunks
                int ci = tid + i * 256;
                int row = ci >> 2, kc = ci & 3;
                cpa16(sb + so + GA_LO + (uint32_t)(row * 80 + kc * 16),
                      Al + (size_t)(m0 + row) * K + kt + kc * 8);
            }
        }
#pragma unroll
        for (int i = 0; i < 2; i++) {                 // B hi: 512 16B chunks
            int ci = tid + i * 256;
            int row = ci >> 2, kc = ci & 3;
            cpa16(sb + so + GB_HI + (uint32_t)(row * 80 + kc * 16),
                  Bh + (size_t)(n0 + row) * K + kt + kc * 8);
        }
        cp_commit();
    };

    auto compute = [&](int c) {
        const uint32_t so = (uint32_t)(c % 3) * GSTAGE;
#pragma unroll
        for (int ks = 0; ks < 2; ks++) {
            const uint32_t kb = (uint32_t)(ks * 32);
            uint32_t aH[4][4], aL[4][4];
#pragma unroll
            for (int mf = 0; mf < 4; mf++) {
                uint32_t ad = sb + so +
                    (uint32_t)((m0w + mf * 16 + (lane & 15)) * 80) +
                    kb + (uint32_t)((lane >> 4) * 16);
                ldm_x4(aH[mf], ad);
                if (needLo) ldm_x4(aL[mf], ad + GA_LO);
            }
#pragma unroll
            for (int nf = 0; nf < 4; nf++) {
                uint32_t bd = sb + so + GB_HI +
                    (uint32_t)((n0w + nf * 8 + (lane & 7)) * 80) +
                    kb + (uint32_t)(((lane >> 3) & 1) * 16);
                uint32_t bH[2];
                ldm_x2(bH, bd);
#pragma unroll
                for (int mf = 0; mf < 4; mf++) {
                    mmaf32(acc[mf][nf], aH[mf], bH);
                    if (needLo) mmaf32(acc[mf][nf], aL[mf], bH);
                }
            }
        }
    };

    const int NC = K / GBK;
    load_stage(0);
    load_stage(1);
    for (int c = 0; c < NC; c++) {
        if (c == NC - 1) cp_wait<0>(); else cp_wait<1>();
        __syncthreads();
        if (c + 2 < NC) load_stage(c + 2);
        compute(c);
    }

    // ---- epilogue ----
#pragma unroll
    for (int mf = 0; mf < 4; mf++) {
        const int r = m0 + m0w + mf * 16 + g;
#pragma unroll
        for (int nf = 0; nf < 4; nf++) {
            const int col = n0 + n0w + nf * 8 + tg * 2;
            const float b0 = bias[col], b1 = bias[col + 1];
#pragma unroll
            for (int half = 0; half < 2; half++) {
                const int rr = r + half * 8;
                const float v0 = acc[mf][nf][half * 2 + 0] + b0;
                const float v1 = acc[mf][nf][half * 2 + 1] + b1;
                if (MODE == 0) {
                    *(float2*)(C + (size_t)rr * N + col) = make_float2(v0, v1);
                } else {
                    if (col < 1024) {                 // Q: hi + lo planes
                        uint32_t hi, lo;
                        packsplith(v0, v1, hi, lo);
                        *(uint32_t*)(qh + (size_t)rr * EMB + col) = hi;
                        *(uint32_t*)(ql + (size_t)rr * EMB + col) = lo;
                    } else if (col < 2048) {          // K: hi only
                        *(uint32_t*)(kh + (size_t)rr * EMB + (col - 1024)) =
                            packh(v0, v1);
                    } else {                          // V: transposed, hi only
                        const int d = col - 2048;
                        const int hh = d >> 6, dd = d & 63;
                        const int bb = rr >> 11, rs = rr & 2047;
                        const size_t vb =
                            ((size_t)(bb * NH + hh) * HD + dd) * SEQ + rs;
                        vth[vb]       = __float2half_rn(v0);
                        vth[vb + SEQ] = __float2half_rn(v1);
                    }
                }
            }
        }
    }
}

// ---------------------------------------------------------------------------
// Flash attention: QK 2-term (Qh+Ql vs Kh), PV 1-term (Ph vs Vh).
// CTA = 128 q rows x (b,h); 8 warps x 16 q rows; KV tiles of 128, double-buffered.
// ---------------------------------------------------------------------------
#define AQ_LO   18432u
#define AKV0    36864u
#define AKV_V   18432u   // within stage
#define AKVSTG  35840u
#define ATT_SMEM (AKV0 + 2u * AKVSTG)   // 108544 bytes

__global__ __launch_bounds__(256, 1)
void attention_mma(const fp16* __restrict__ qh, const fp16* __restrict__ ql,
                   const fp16* __restrict__ kh, const fp16* __restrict__ vth,
                   fp16* __restrict__ ath, fp16* __restrict__ atl,
                   const int* __restrict__ causal_flag)
{
    extern __shared__ __align__(16) char sm[];
    const uint32_t sb = smem_u32(sm);
    const int tid = threadIdx.x, wid = tid >> 5, lane = tid & 31;
    const int g = lane >> 2, tg = lane & 3;
    const int qt = (SEQ / 128 - 1) - blockIdx.x;   // long CTAs first
    const int bh = blockIdx.y, b = bh / NH, h = bh % NH;
    const int causal = *causal_flag;
    const int q0 = qt * 128;

    auto load_kv = [&](int kvt, int st) {
        const int kv0 = kvt * 128;
        const uint32_t so = AKV0 + (uint32_t)st * AKVSTG;
#pragma unroll
        for (int i = 0; i < 4; i++) {            // K hi: 1024 chunks
            int ci = tid + i * 256;
            int row = ci >> 3, kc = ci & 7;
            const fp16* src = kh + (size_t)(b * SEQ + kv0 + row) * EMB +
                              h * HD + kc * 8;
            cpa16(sb + so + (uint32_t)(row * 144 + kc * 16), src);
        }
#pragma unroll
        for (int i = 0; i < 4; i++) {            // V hi: 1024 chunks
            int ci = tid + i * 256;
            int row = ci >> 4, kc = ci & 15;
            const fp16* src = vth + ((size_t)bh * HD + row) * SEQ + kv0 + kc * 8;
            cpa16(sb + so + AKV_V + (uint32_t)(row * 272 + kc * 16), src);
        }
        cp_commit();
    };

    // ---- prologue: Q hi/lo + KV(0) ----
#pragma unroll
    for (int i = 0; i < 8; i++) {
        int ci = tid + i * 256;
        int row = ci >> 4, sub = ci & 15;
        int pl = sub >> 3, kc = sub & 7;
        const fp16* src = (pl ? ql : qh) +
            (size_t)(b * SEQ + q0 + row) * EMB + h * HD + kc * 8;
        cpa16(sb + (pl ? AQ_LO : 0u) + (uint32_t)(row * 144 + kc * 16), src);
    }
    load_kv(0, 0);

    float o[8][4];
#pragma unroll
    for (int i = 0; i < 8; i++)
#pragma unroll
        for (int e = 0; e < 4; e++) o[i][e] = 0.0f;
    float m0v = -1e30f, m1v = -1e30f, l0v = 0.0f, l1v = 0.0f;

    const int nkv = causal ? (qt + 1) : (SEQ / 128);
    for (int kvt = 0; kvt < nkv; kvt++) {
        cp_wait<0>();
        __syncthreads();
        if (kvt + 1 < nkv) load_kv(kvt + 1, (kvt + 1) & 1);  // overlaps compute

        const uint32_t kvb = AKV0 + (uint32_t)(kvt & 1) * AKVSTG;

        // ---- S = (Qh+Ql) @ Kh^T ----
        float s[16][4];
#pragma unroll
        for (int nf = 0; nf < 16; nf++)
#pragma unroll
            for (int e = 0; e < 4; e++) s[nf][e] = 0.0f;

#pragma unroll
        for (int ks = 0; ks < 4; ks++) {
            const uint32_t kb = (uint32_t)(ks * 32);
            uint32_t aH[4], aL[4];
            uint32_t ad = sb + (uint32_t)((wid * 16 + (lane & 15)) * 144) +
                          kb + (uint32_t)((lane >> 4) * 16);
            ldm_x4(aH, ad);
            ldm_x4(aL, ad + AQ_LO);
#pragma unroll
            for (int nf = 0; nf < 16; nf++) {
                uint32_t bd = sb + kvb +
                    (uint32_t)((nf * 8 + (lane & 7)) * 144) +
                    kb + (uint32_t)(((lane >> 3) & 1) * 16);
                uint32_t bH[2];
                ldm_x2(bH, bd);
                mmaf32(s[nf], aH, bH);
                mmaf32(s[nf], aL, bH);
            }
        }

        // ---- scale + causal mask (diagonal tile only) ----
        const bool dm = (causal != 0) && (kvt == qt);
#pragma unroll
        for (int nf = 0; nf < 16; nf++) {
#pragma unroll
            for (int e = 0; e < 4; e++) {
                float v = s[nf][e] * 0.125f;   // 1/sqrt(64)
                if (dm) {
                    int qr = wid * 16 + g + ((e >= 2) ? 8 : 0);
                    int kc = nf * 8 + tg * 2 + (e & 1);
                    if (kc > qr) v = -1e30f;
                }
                s[nf][e] = v;
            }
        }

        // ---- online softmax (rows g and g+8) ----
        float mx0 = -1e30f, mx1 = -1e30f;
#pragma unroll
        for (int nf = 0; nf < 16; nf++) {
            mx0 = fmaxf(mx0, fmaxf(s[nf][0], s[nf][1]));
            mx1 = fmaxf(mx1, fmaxf(s[nf][2], s[nf][3]));
        }
        mx0 = fmaxf(mx0, __shfl_xor_sync(0xffffffffu, mx0, 1));
        mx0 = fmaxf(mx0, __shfl_xor_sync(0xffffffffu, mx0, 2));
        mx1 = fmaxf(mx1, __shfl_xor_sync(0xffffffffu, mx1, 1));
        mx1 = fmaxf(mx1, __shfl_xor_sync(0xffffffffu, mx1, 2));

        const float mn0 = fmaxf(m0v, mx0), mn1 = fmaxf(m1v, mx1);
        const float al0 = __expf(m0v - mn0), al1 = __expf(m1v - mn1);
        m0v = mn0; m1v = mn1;

        float rs0 = 0.0f, rs1 = 0.0f;
#pragma unroll
        for (int nf = 0; nf < 16; nf++) {
            s[nf][0] = __expf(s[nf][0] - mn0); rs0 += s[nf][0];
            s[nf][1] = __expf(s[nf][1] - mn0); rs0 += s[nf][1];
            s[nf][2] = __expf(s[nf][2] - mn1); rs1 += s[nf][2];
            s[nf][3] = __expf(s[nf][3] - mn1); rs1 += s[nf][3];
        }
        rs0 += __shfl_xor_sync(0xffffffffu, rs0, 1);
        rs0 += __shfl_xor_sync(0xffffffffu, rs0, 2);
        rs1 += __shfl_xor_sync(0xffffffffu, rs1, 1);
        rs1 += __shfl_xor_sync(0xffffffffu, rs1, 2);
        l0v = l0v * al0 + rs0;
        l1v = l1v * al1 + rs1;

#pragma unroll
        for (int nf = 0; nf < 8; nf++) {
            o[nf][0] *= al0; o[nf][1] *= al0;
            o[nf][2] *= al1; o[nf][3] *= al1;
        }

        // ---- O += Ph @ Vh (1-term P; V^T frags via ldmatrix) ----
#pragma unroll
        for (int kf = 0; kf < 8; kf++) {
            uint32_t aH[4];
            aH[0] = packh(s[2 * kf][0],     s[2 * kf][1]);
            aH[1] = packh(s[2 * kf][2],     s[2 * kf][3]);
            aH[2] = packh(s[2 * kf + 1][0], s[2 * kf + 1][1]);
            aH[3] = packh(s[2 * kf + 1][2], s[2 * kf + 1][3]);
#pragma unroll
            for (int nf = 0; nf < 8; nf++) {
                uint32_t vd = sb + kvb + AKV_V +
                    (uint32_t)((nf * 8 + (lane & 7)) * 272) +
                    (uint32_t)(kf * 32) + (uint32_t)(((lane >> 3) & 1) * 16);
                uint32_t bH[2];
                ldm_x2(bH, vd);
                mmaf32(o[nf], aH, bH);
            }
        }
        __syncthreads();   // all warps done with stage before next overwrite
    }

    // ---- normalize + write hi/lo fp16 planes of O ----
    const float inv0 = 1.0f / l0v, inv1 = 1.0f / l1v;
    const size_t r0 = (size_t)(b * SEQ + q0 + wid * 16 + g);
#pragma unroll
    for (int nf = 0; nf < 8; nf++) {
        const int col = h * HD + nf * 8 + tg * 2;
        uint32_t hi, lo;
        packsplith(o[nf][0] * inv0, o[nf][1] * inv0, hi, lo);
        *(uint32_t*)(ath + r0 * EMB + col) = hi;
        *(uint32_t*)(atl + r0 * EMB + col) = lo;
        packsplith(o[nf][2] * inv1, o[nf][3] * inv1, hi, lo);
        *(uint32_t*)(ath + (r0 + 8) * EMB + col) = hi;
        *(uint32_t*)(atl + (r0 + 8) * EMB + col) = lo;
    }
}

// ---------------------------------------------------------------------------
extern "C" void kernel_launch(void* const* d_in, const int* in_sizes, int n_in,
                              void* d_out, int out_size)
{
    (void)in_sizes; (void)n_in; (void)out_size;
    const float* x      = (const float*)d_in[0];
    const float* w_qkv  = (const float*)d_in[1];
    const float* b_qkv  = (const float*)d_in[2];
    const float* w_out  = (const float*)d_in[3];
    const float* b_out  = (const float*)d_in[4];
    const int*   causal = (const int*)d_in[5];
    float* out = (float*)d_out;

    fp16 *xh, *xl, *wqh, *woh, *qh, *ql, *kh, *vth, *ath, *atl;
    cudaGetSymbolAddress((void**)&xh,  g_xh);   cudaGetSymbolAddress((void**)&xl,  g_xl);
    cudaGetSymbolAddress((void**)&wqh, g_wqh);  cudaGetSymbolAddress((void**)&woh, g_woh);
    cudaGetSymbolAddress((void**)&qh,  g_qh);   cudaGetSymbolAddress((void**)&ql,  g_ql);
    cudaGetSymbolAddress((void**)&kh,  g_kh);   cudaGetSymbolAddress((void**)&vth, g_vth);
    cudaGetSymbolAddress((void**)&ath, g_ath);  cudaGetSymbolAddress((void**)&atl, g_atl);

    cudaFuncSetAttribute(gemm_2t<0>, cudaFuncAttributeMaxDynamicSharedMemorySize,
                         (int)GEMM_SMEM);
    cudaFuncSetAttribute(gemm_2t<1>, cudaFuncAttributeMaxDynamicSharedMemorySize,
                         (int)GEMM_SMEM);
    cudaFuncSetAttribute(attention_mma, cudaFuncAttributeMaxDynamicSharedMemorySize,
                         (int)ATT_SMEM);

    // 1) pre-convert: x -> hi/lo planes; weights -> hi plane only
    convert_split<<<(MTOT * EMB / 4 + 255) / 256, 256>>>(
        (const float4*)x, (uint2*)xh, (uint2*)xl, MTOT * EMB / 4);
    convert_hi<<<(NQKV * EMB / 4 + 255) / 256, 256>>>(
        (const float4*)w_qkv, (uint2*)wqh, NQKV * EMB / 4);
    convert_hi<<<(EMB * EMB / 4 + 255) / 256, 256>>>(
        (const float4*)w_out, (uint2*)woh, EMB * EMB / 4);

    // 2) QKV projection -> Q hi/lo (2-term A), K hi, V^T hi (1-term A)
    gemm_2t<1><<<dim3(NQKV / GBN, MTOT / GBM), 256, GEMM_SMEM>>>(
        xh, xl, wqh, b_qkv, nullptr, qh, ql, kh, vth, MTOT, NQKV, EMB);

    // 3) causal flash attention -> O hi/lo planes
    attention_mma<<<dim3(SEQ / 128, BATCH * NH), 256, ATT_SMEM>>>(
        qh, ql, kh, vth, ath, atl, causal);

    // 4) output projection -> fp32 out (2-term A)
    gemm_2t<0><<<dim3(EMB / GBN, MTOT / GBM), 256, GEMM_SMEM>>>(
        ath, atl, woh, b_out, out, nullptr, nullptr, nullptr, nullptr,
        MTOT, EMB, EMB);
}

// round 13
// speedup vs baseline: 1.5911x; 1.4320x over previous
#include <cuda_runtime.h>
#include <cuda_fp16.h>
#include <cstdint>

typedef __half fp16;

// Problem constants
#define BATCH 2
#define SEQ   2048
#define EMB   1024
#define NH    16
#define HD    64
#define MTOT  (BATCH * SEQ)     // 4096
#define NQKV  (3 * EMB)         // 3072

// ---------------------------------------------------------------------------
// Device-global scratch (allocation-free rule)
// ---------------------------------------------------------------------------
__device__ fp16 g_xh[(size_t)MTOT * EMB];                  // x: hi only
__device__ fp16 g_wqh[(size_t)NQKV * EMB];                 // weights: hi only
__device__ fp16 g_woh[(size_t)EMB * EMB];
__device__ fp16 g_qh[(size_t)MTOT * EMB], g_ql[(size_t)MTOT * EMB];   // Q planes
__device__ fp16 g_kh[(size_t)MTOT * EMB];                  // K: hi only
__device__ fp16 g_vth[(size_t)BATCH * NH * HD * SEQ];      // V^T: hi only
__device__ fp16 g_ath[(size_t)MTOT * EMB];                 // attn out: hi only

// ---------------------------------------------------------------------------
// Helpers
// ---------------------------------------------------------------------------
__device__ __forceinline__ uint32_t smem_u32(const void* p) {
    uint32_t a;
    asm("{ .reg .u64 t; cvta.to.shared.u64 t, %1; cvt.u32.u64 %0, t; }"
        : "=r"(a) : "l"(p));
    return a;
}
// fp16 split: (x,y) -> hi pair (rounded), lo pair (residual)
__device__ __forceinline__ void packsplith(float x, float y,
                                           uint32_t& hi, uint32_t& lo) {
    __half2 h = __floats2half2_rn(x, y);
    float2 hf = __half22float2(h);
    __half2 l = __floats2half2_rn(x - hf.x, y - hf.y);
    hi = *reinterpret_cast<uint32_t*>(&h);
    lo = *reinterpret_cast<uint32_t*>(&l);
}
__device__ __forceinline__ uint32_t packh(float x, float y) {
    __half2 h = __floats2half2_rn(x, y);
    return *reinterpret_cast<uint32_t*>(&h);
}

// fp16 inputs, fp32 accum
__device__ __forceinline__ void mmaf32(float* d, const uint32_t* a,
                                       const uint32_t* b) {
    asm volatile(
        "mma.sync.aligned.m16n8k16.row.col.f32.f16.f16.f32 "
        "{%0,%1,%2,%3}, {%4,%5,%6,%7}, {%8,%9}, {%0,%1,%2,%3};"
        : "+f"(d[0]), "+f"(d[1]), "+f"(d[2]), "+f"(d[3])
        : "r"(a[0]), "r"(a[1]), "r"(a[2]), "r"(a[3]), "r"(b[0]), "r"(b[1]));
}
__device__ __forceinline__ void ldm_x4(uint32_t* r, uint32_t addr) {
    asm volatile("ldmatrix.sync.aligned.m8n8.x4.shared.b16 {%0,%1,%2,%3}, [%4];"
                 : "=r"(r[0]), "=r"(r[1]), "=r"(r[2]), "=r"(r[3]) : "r"(addr));
}
__device__ __forceinline__ void ldm_x2(uint32_t* r, uint32_t addr) {
    asm volatile("ldmatrix.sync.aligned.m8n8.x2.shared.b16 {%0,%1}, [%2];"
                 : "=r"(r[0]), "=r"(r[1]) : "r"(addr));
}
__device__ __forceinline__ void cpa16(uint32_t dst, const void* src) {
    asm volatile("cp.async.cg.shared.global [%0], [%1], 16;" :: "r"(dst), "l"(src));
}
__device__ __forceinline__ void cp_commit() {
    asm volatile("cp.async.commit_group;" ::: "memory");
}
template <int N>
__device__ __forceinline__ void cp_wait() {
    asm volatile("cp.async.wait_group %0;" :: "n"(N) : "memory");
}

// ---------------------------------------------------------------------------
// Pre-convert: fp32 -> fp16 hi plane
// ---------------------------------------------------------------------------
__global__ void convert_hi(const float4* __restrict__ in,
                           uint2* __restrict__ hi, int n4)
{
    int i = blockIdx.x * blockDim.x + threadIdx.x;
    if (i >= n4) return;
    float4 v = in[i];
    hi[i] = make_uint2(packh(v.x, v.y), packh(v.z, v.w));
}

// ---------------------------------------------------------------------------
// 1-term fp16 GEMM: C[M,N] = Ah[M,K] @ Bh[N,K]^T + bias[N]
// CTA 128x128, BK=32, 8 warps (2m x 4n), 3-stage cp.async ring, 2 CTAs/SM.
// MODE 0: fp32 C out.  MODE 1: QKV out (Q hi/lo planes, K hi, V^T hi).
// ---------------------------------------------------------------------------
#define GBM 128
#define GBN 128
#define GBK 32
#define GB_OFF 10240u
#define GSTAGE 20480u
#define GEMM_SMEM (3u * GSTAGE)   // 61440 bytes -> 2 CTAs/SM

template <int MODE>
__global__ __launch_bounds__(256, 2)
void gemm_1t(const fp16* __restrict__ Ah, const fp16* __restrict__ Bh,
             const float* __restrict__ bias, float* __restrict__ C,
             fp16* __restrict__ qh, fp16* __restrict__ ql,
             fp16* __restrict__ kh, fp16* __restrict__ vth,
             int M, int N, int K)
{
    extern __shared__ __align__(16) char sm[];
    const uint32_t sb = smem_u32(sm);
    const int tid = threadIdx.x;
    const int wid = tid >> 5, lane = tid & 31;
    const int g = lane >> 2, tg = lane & 3;
    const int m0 = blockIdx.y * GBM, n0 = blockIdx.x * GBN;
    const int m0w = (wid >> 2) * 64, n0w = (wid & 3) * 32;

    float acc[4][4][4];
#pragma unroll
    for (int i = 0; i < 4; i++)
#pragma unroll
        for (int j = 0; j < 4; j++)
#pragma unroll
            for (int e = 0; e < 4; e++) acc[i][j][e] = 0.0f;

    auto load_stage = [&](int c) {
        const int kt = c * GBK;
        const uint32_t so = (uint32_t)(c % 3) * GSTAGE;
#pragma unroll
        for (int i = 0; i < 2; i++) {                 // A hi: 512 16B chunks
            int ci = tid + i * 256;
            int row = ci >> 2, kc = ci & 3;
            cpa16(sb + so + (uint32_t)(row * 80 + kc * 16),
                  Ah + (size_t)(m0 + row) * K + kt + kc * 8);
        }
#pragma unroll
        for (int i = 0; i < 2; i++) {                 // B hi: 512 16B chunks
            int ci = tid + i * 256;
            int row = ci >> 2, kc = ci & 3;
            cpa16(sb + so + GB_OFF + (uint32_t)(row * 80 + kc * 16),
                  Bh + (size_t)(n0 + row) * K + kt + kc * 8);
        }
        cp_commit();
    };

    auto compute = [&](int c) {
        const uint32_t so = (uint32_t)(c % 3) * GSTAGE;
#pragma unroll
        for (int ks = 0; ks < 2; ks++) {
            const uint32_t kb = (uint32_t)(ks * 32);
            uint32_t aH[4][4];
#pragma unroll
            for (int mf = 0; mf < 4; mf++) {
                uint32_t ad = sb + so +
                    (uint32_t)((m0w + mf * 16 + (lane & 15)) * 80) +
                    kb + (uint32_t)((lane >> 4) * 16);
                ldm_x4(aH[mf], ad);
            }
#pragma unroll
            for (int nf = 0; nf < 4; nf++) {
                uint32_t bd = sb + so + GB_OFF +
                    (uint32_t)((n0w + nf * 8 + (lane & 7)) * 80) +
                    kb + (uint32_t)(((lane >> 3) & 1) * 16);
                uint32_t bH[2];
                ldm_x2(bH, bd);
#pragma unroll
                for (int mf = 0; mf < 4; mf++)
                    mmaf32(acc[mf][nf], aH[mf], bH);
            }
        }
    };

    const int NC = K / GBK;
    load_stage(0);
    load_stage(1);
    for (int c = 0; c < NC; c++) {
        if (c == NC - 1) cp_wait<0>(); else cp_wait<1>();
        __syncthreads();
        if (c + 2 < NC) load_stage(c + 2);
        compute(c);
    }

    // ---- epilogue ----
#pragma unroll
    for (int mf = 0; mf < 4; mf++) {
        const int r = m0 + m0w + mf * 16 + g;
#pragma unroll
        for (int nf = 0; nf < 4; nf++) {
            const int col = n0 + n0w + nf * 8 + tg * 2;
            const float b0 = bias[col], b1 = bias[col + 1];
#pragma unroll
            for (int half = 0; half < 2; half++) {
                const int rr = r + half * 8;
                const float v0 = acc[mf][nf][half * 2 + 0] + b0;
                const float v1 = acc[mf][nf][half * 2 + 1] + b1;
                if (MODE == 0) {
                    *(float2*)(C + (size_t)rr * N + col) = make_float2(v0, v1);
                } else {
                    if (col < 1024) {                 // Q: hi + lo planes
                        uint32_t hi, lo;
                        packsplith(v0, v1, hi, lo);
                        *(uint32_t*)(qh + (size_t)rr * EMB + col) = hi;
                        *(uint32_t*)(ql + (size_t)rr * EMB + col) = lo;
                    } else if (col < 2048) {          // K: hi only
                        *(uint32_t*)(kh + (size_t)rr * EMB + (col - 1024)) =
                            packh(v0, v1);
                    } else {                          // V: transposed, hi only
                        const int d = col - 2048;
                        const int hh = d >> 6, dd = d & 63;
                        const int bb = rr >> 11, rs = rr & 2047;
                        const size_t vb =
                            ((size_t)(bb * NH + hh) * HD + dd) * SEQ + rs;
                        vth[vb]       = __float2half_rn(v0);
                        vth[vb + SEQ] = __float2half_rn(v1);
                    }
                }
            }
        }
    }
}

// ---------------------------------------------------------------------------
// Flash attention: QK 2-term (Qh+Ql vs Kh), PV 1-term (Ph vs Vh).
// CTA = 128 q rows x (b,h); 8 warps x 16 q rows; KV tiles of 128, double-buffered.
// Output: hi plane only.
// ---------------------------------------------------------------------------
#define AQ_LO   18432u
#define AKV0    36864u
#define AKV_V   18432u   // within stage
#define AKVSTG  35840u
#define ATT_SMEM (AKV0 + 2u * AKVSTG)   // 108544 bytes

__global__ __launch_bounds__(256, 1)
void attention_mma(const fp16* __restrict__ qh, const fp16* __restrict__ ql,
                   const fp16* __restrict__ kh, const fp16* __restrict__ vth,
                   fp16* __restrict__ ath,
                   const int* __restrict__ causal_flag)
{
    extern __shared__ __align__(16) char sm[];
    const uint32_t sb = smem_u32(sm);
    const int tid = threadIdx.x, wid = tid >> 5, lane = tid & 31;
    const int g = lane >> 2, tg = lane & 3;
    const int qt = (SEQ / 128 - 1) - blockIdx.x;   // long CTAs first
    const int bh = blockIdx.y, b = bh / NH, h = bh % NH;
    const int causal = *causal_flag;
    const int q0 = qt * 128;

    auto load_kv = [&](int kvt, int st) {
        const int kv0 = kvt * 128;
        const uint32_t so = AKV0 + (uint32_t)st * AKVSTG;
#pragma unroll
        for (int i = 0; i < 4; i++) {            // K hi: 1024 chunks
            int ci = tid + i * 256;
            int row = ci >> 3, kc = ci & 7;
            const fp16* src = kh + (size_t)(b * SEQ + kv0 + row) * EMB +
                              h * HD + kc * 8;
            cpa16(sb + so + (uint32_t)(row * 144 + kc * 16), src);
        }
#pragma unroll
        for (int i = 0; i < 4; i++) {            // V hi: 1024 chunks
            int ci = tid + i * 256;
            int row = ci >> 4, kc = ci & 15;
            const fp16* src = vth + ((size_t)bh * HD + row) * SEQ + kv0 + kc * 8;
            cpa16(sb + so + AKV_V + (uint32_t)(row * 272 + kc * 16), src);
        }
        cp_commit();
    };

    // ---- prologue: Q hi/lo + KV(0) ----
#pragma unroll
    for (int i = 0; i < 8; i++) {
        int ci = tid + i * 256;
        int row = ci >> 4, sub = ci & 15;
        int pl = sub >> 3, kc = sub & 7;
        const fp16* src = (pl ? ql : qh) +
            (size_t)(b * SEQ + q0 + row) * EMB + h * HD + kc * 8;
        cpa16(sb + (pl ? AQ_LO : 0u) + (uint32_t)(row * 144 + kc * 16), src);
    }
    load_kv(0, 0);

    float o[8][4];
#pragma unroll
    for (int i = 0; i < 8; i++)
#pragma unroll
        for (int e = 0; e < 4; e++) o[i][e] = 0.0f;
    float m0v = -1e30f, m1v = -1e30f, l0v = 0.0f, l1v = 0.0f;

    const int nkv = causal ? (qt + 1) : (SEQ / 128);
    for (int kvt = 0; kvt < nkv; kvt++) {
        cp_wait<0>();
        __syncthreads();
        if (kvt + 1 < nkv) load_kv(kvt + 1, (kvt + 1) & 1);  // overlaps compute

        const uint32_t kvb = AKV0 + (uint32_t)(kvt & 1) * AKVSTG;

        // ---- S = (Qh+Ql) @ Kh^T ----
        float s[16][4];
#pragma unroll
        for (int nf = 0; nf < 16; nf++)
#pragma unroll
            for (int e = 0; e < 4; e++) s[nf][e] = 0.0f;

#pragma unroll
        for (int ks = 0; ks < 4; ks++) {
            const uint32_t kb = (uint32_t)(ks * 32);
            uint32_t aH[4], aL[4];
            uint32_t ad = sb + (uint32_t)((wid * 16 + (lane & 15)) * 144) +
                          kb + (uint32_t)((lane >> 4) * 16);
            ldm_x4(aH, ad);
            ldm_x4(aL, ad + AQ_LO);
#pragma unroll
            for (int nf = 0; nf < 16; nf++) {
                uint32_t bd = sb + kvb +
                    (uint32_t)((nf * 8 + (lane & 7)) * 144) +
                    kb + (uint32_t)(((lane >> 3) & 1) * 16);
                uint32_t bH[2];
                ldm_x2(bH, bd);
                mmaf32(s[nf], aH, bH);
                mmaf32(s[nf], aL, bH);
            }
        }

        // ---- scale + causal mask (diagonal tile only) ----
        const bool dm = (causal != 0) && (kvt == qt);
#pragma unroll
        for (int nf = 0; nf < 16; nf++) {
#pragma unroll
            for (int e = 0; e < 4; e++) {
                float v = s[nf][e] * 0.125f;   // 1/sqrt(64)
                if (dm) {
                    int qr = wid * 16 + g + ((e >= 2) ? 8 : 0);
                    int kc = nf * 8 + tg * 2 + (e & 1);
                    if (kc > qr) v = -1e30f;
                }
                s[nf][e] = v;
            }
        }

        // ---- online softmax (rows g and g+8) ----
        float mx0 = -1e30f, mx1 = -1e30f;
#pragma unroll
        for (int nf = 0; nf < 16; nf++) {
            mx0 = fmaxf(mx0, fmaxf(s[nf][0], s[nf][1]));
            mx1 = fmaxf(mx1, fmaxf(s[nf][2], s[nf][3]));
        }
        mx0 = fmaxf(mx0, __shfl_xor_sync(0xffffffffu, mx0, 1));
        mx0 = fmaxf(mx0, __shfl_xor_sync(0xffffffffu, mx0, 2));
        mx1 = fmaxf(mx1, __shfl_xor_sync(0xffffffffu, mx1, 1));
        mx1 = fmaxf(mx1, __shfl_xor_sync(0xffffffffu, mx1, 2));

        const float mn0 = fmaxf(m0v, mx0), mn1 = fmaxf(m1v, mx1);
        const float al0 = __expf(m0v - mn0), al1 = __expf(m1v - mn1);
        m0v = mn0; m1v = mn1;

        float rs0 = 0.0f, rs1 = 0.0f;
#pragma unroll
        for (int nf = 0; nf < 16; nf++) {
            s[nf][0] = __expf(s[nf][0] - mn0); rs0 += s[nf][0];
            s[nf][1] = __expf(s[nf][1] - mn0); rs0 += s[nf][1];
            s[nf][2] = __expf(s[nf][2] - mn1); rs1 += s[nf][2];
            s[nf][3] = __expf(s[nf][3] - mn1); rs1 += s[nf][3];
        }
        rs0 += __shfl_xor_sync(0xffffffffu, rs0, 1);
        rs0 += __shfl_xor_sync(0xffffffffu, rs0, 2);
        rs1 += __shfl_xor_sync(0xffffffffu, rs1, 1);
        rs1 += __shfl_xor_sync(0xffffffffu, rs1, 2);
        l0v = l0v * al0 + rs0;
        l1v = l1v * al1 + rs1;

#pragma unroll
        for (int nf = 0; nf < 8; nf++) {
            o[nf][0] *= al0; o[nf][1] *= al0;
            o[nf][2] *= al1; o[nf][3] *= al1;
        }

        // ---- O += Ph @ Vh (1-term P; V^T frags via ldmatrix) ----
#pragma unroll
        for (int kf = 0; kf < 8; kf++) {
            uint32_t aH[4];
            aH[0] = packh(s[2 * kf][0],     s[2 * kf][1]);
            aH[1] = packh(s[2 * kf][2],     s[2 * kf][3]);
            aH[2] = packh(s[2 * kf + 1][0], s[2 * kf + 1][1]);
            aH[3] = packh(s[2 * kf + 1][2], s[2 * kf + 1][3]);
#pragma unroll
            for (int nf = 0; nf < 8; nf++) {
                uint32_t vd = sb + kvb + AKV_V +
                    (uint32_t)((nf * 8 + (lane & 7)) * 272) +
                    (uint32_t)(kf * 32) + (uint32_t)(((lane >> 3) & 1) * 16);
                uint32_t bH[2];
                ldm_x2(bH, vd);
                mmaf32(o[nf], aH, bH);
            }
        }
        __syncthreads();   // all warps done with stage before next overwrite
    }

    // ---- normalize + write hi fp16 plane of O ----
    const float inv0 = 1.0f / l0v, inv1 = 1.0f / l1v;
    const size_t r0 = (size_t)(b * SEQ + q0 + wid * 16 + g);
#pragma unroll
    for (int nf = 0; nf < 8; nf++) {
        const int col = h * HD + nf * 8 + tg * 2;
        *(uint32_t*)(ath + r0 * EMB + col) =
            packh(o[nf][0] * inv0, o[nf][1] * inv0);
        *(uint32_t*)(ath + (r0 + 8) * EMB + col) =
            packh(o[nf][2] * inv1, o[nf][3] * inv1);
    }
}

// ---------------------------------------------------------------------------
extern "C" void kernel_launch(void* const* d_in, const int* in_sizes, int n_in,
                              void* d_out, int out_size)
{
    (void)in_sizes; (void)n_in; (void)out_size;
    const float* x      = (const float*)d_in[0];
    const float* w_qkv  = (const float*)d_in[1];
    const float* b_qkv  = (const float*)d_in[2];
    const float* w_out  = (const float*)d_in[3];
    const float* b_out  = (const float*)d_in[4];
    const int*   causal = (const int*)d_in[5];
    float* out = (float*)d_out;

    fp16 *xh, *wqh, *woh, *qh, *ql, *kh, *vth, *ath;
    cudaGetSymbolAddress((void**)&xh,  g_xh);
    cudaGetSymbolAddress((void**)&wqh, g_wqh);  cudaGetSymbolAddress((void**)&woh, g_woh);
    cudaGetSymbolAddress((void**)&qh,  g_qh);   cudaGetSymbolAddress((void**)&ql,  g_ql);
    cudaGetSymbolAddress((void**)&kh,  g_kh);   cudaGetSymbolAddress((void**)&vth, g_vth);
    cudaGetSymbolAddress((void**)&ath, g_ath);

    cudaFuncSetAttribute(gemm_1t<0>, cudaFuncAttributeMaxDynamicSharedMemorySize,
                         (int)GEMM_SMEM);
    cudaFuncSetAttribute(gemm_1t<1>, cudaFuncAttributeMaxDynamicSharedMemorySize,
                         (int)GEMM_SMEM);
    cudaFuncSetAttribute(attention_mma, cudaFuncAttributeMaxDynamicSharedMemorySize,
                         (int)ATT_SMEM);

    // 1) pre-convert: all inputs -> fp16 hi planes
    convert_hi<<<(MTOT * EMB / 4 + 255) / 256, 256>>>(
        (const float4*)x, (uint2*)xh, MTOT * EMB / 4);
    convert_hi<<<(NQKV * EMB / 4 + 255) / 256, 256>>>(
        (const float4*)w_qkv, (uint2*)wqh, NQKV * EMB / 4);
    convert_hi<<<(EMB * EMB / 4 + 255) / 256, 256>>>(
        (const float4*)w_out, (uint2*)woh, EMB * EMB / 4);

    // 2) QKV projection (1-term) -> Q hi/lo, K hi, V^T hi
    gemm_1t<1><<<dim3(NQKV / GBN, MTOT / GBM), 256, GEMM_SMEM>>>(
        xh, wqh, b_qkv, nullptr, qh, ql, kh, vth, MTOT, NQKV, EMB);

    // 3) causal flash attention -> O hi plane
    attention_mma<<<dim3(SEQ / 128, BATCH * NH), 256, ATT_SMEM>>>(
        qh, ql, kh, vth, ath, causal);

    // 4) output projection (1-term) -> fp32 out
    gemm_1t<0><<<dim3(EMB / GBN, MTOT / GBM), 256, GEMM_SMEM>>>(
        ath, woh, b_out, out, nullptr, nullptr, nullptr, nullptr,
        MTOT, EMB, EMB);
}

// round 14
// speedup vs baseline: 1.7180x; 1.0797x over previous
#include <cuda_runtime.h>
#include <cuda_fp16.h>
#include <cstdint>

typedef __half fp16;

// Problem constants
#define BATCH 2
#define SEQ   2048
#define EMB   1024
#define NH    16
#define HD    64
#define MTOT  (BATCH * SEQ)     // 4096
#define NQKV  (3 * EMB)         // 3072

// ---------------------------------------------------------------------------
// Device-global scratch (allocation-free rule)
// ---------------------------------------------------------------------------
__device__ fp16 g_xh[(size_t)MTOT * EMB];                  // x: hi only
__device__ fp16 g_wqh[(size_t)NQKV * EMB];                 // weights: hi only
__device__ fp16 g_woh[(size_t)EMB * EMB];
__device__ fp16 g_qh[(size_t)MTOT * EMB];                  // Q: hi only
__device__ fp16 g_kh[(size_t)MTOT * EMB];                  // K: hi only
__device__ fp16 g_vth[(size_t)BATCH * NH * HD * SEQ];      // V^T: hi only
__device__ fp16 g_ath[(size_t)MTOT * EMB];                 // attn out: hi only

// ---------------------------------------------------------------------------
// Helpers
// ---------------------------------------------------------------------------
__device__ __forceinline__ uint32_t smem_u32(const void* p) {
    uint32_t a;
    asm("{ .reg .u64 t; cvta.to.shared.u64 t, %1; cvt.u32.u64 %0, t; }"
        : "=r"(a) : "l"(p));
    return a;
}
__device__ __forceinline__ uint32_t packh(float x, float y) {
    __half2 h = __floats2half2_rn(x, y);
    return *reinterpret_cast<uint32_t*>(&h);
}

// fp16 inputs, fp32 accum
__device__ __forceinline__ void mmaf32(float* d, const uint32_t* a,
                                       const uint32_t* b) {
    asm volatile(
        "mma.sync.aligned.m16n8k16.row.col.f32.f16.f16.f32 "
        "{%0,%1,%2,%3}, {%4,%5,%6,%7}, {%8,%9}, {%0,%1,%2,%3};"
        : "+f"(d[0]), "+f"(d[1]), "+f"(d[2]), "+f"(d[3])
        : "r"(a[0]), "r"(a[1]), "r"(a[2]), "r"(a[3]), "r"(b[0]), "r"(b[1]));
}
__device__ __forceinline__ void ldm_x4(uint32_t* r, uint32_t addr) {
    asm volatile("ldmatrix.sync.aligned.m8n8.x4.shared.b16 {%0,%1,%2,%3}, [%4];"
                 : "=r"(r[0]), "=r"(r[1]), "=r"(r[2]), "=r"(r[3]) : "r"(addr));
}
__device__ __forceinline__ void ldm_x2(uint32_t* r, uint32_t addr) {
    asm volatile("ldmatrix.sync.aligned.m8n8.x2.shared.b16 {%0,%1}, [%2];"
                 : "=r"(r[0]), "=r"(r[1]) : "r"(addr));
}
__device__ __forceinline__ void cpa16(uint32_t dst, const void* src) {
    asm volatile("cp.async.cg.shared.global [%0], [%1], 16;" :: "r"(dst), "l"(src));
}
__device__ __forceinline__ void cp_commit() {
    asm volatile("cp.async.commit_group;" ::: "memory");
}
template <int N>
__device__ __forceinline__ void cp_wait() {
    asm volatile("cp.async.wait_group %0;" :: "n"(N) : "memory");
}

// ---------------------------------------------------------------------------
// Pre-convert: fp32 -> fp16 hi plane
// ---------------------------------------------------------------------------
__global__ void convert_hi(const float4* __restrict__ in,
                           uint2* __restrict__ hi, int n4)
{
    int i = blockIdx.x * blockDim.x + threadIdx.x;
    if (i >= n4) return;
    float4 v = in[i];
    hi[i] = make_uint2(packh(v.x, v.y), packh(v.z, v.w));
}

// ---------------------------------------------------------------------------
// 1-term fp16 GEMM: C[M,N] = Ah[M,K] @ Bh[N,K]^T + bias[N]
// CTA 128x128, BK=32, 8 warps (2m x 4n), 3-stage cp.async ring, 2 CTAs/SM.
// MODE 0: fp32 C out.  MODE 1: QKV out (Q hi, K hi, V^T hi).
// ---------------------------------------------------------------------------
#define GBM 128
#define GBN 128
#define GBK 32
#define GB_OFF 10240u
#define GSTAGE 20480u
#define GEMM_SMEM (3u * GSTAGE)   // 61440 bytes -> 2 CTAs/SM

template <int MODE>
__global__ __launch_bounds__(256, 2)
void gemm_1t(const fp16* __restrict__ Ah, const fp16* __restrict__ Bh,
             const float* __restrict__ bias, float* __restrict__ C,
             fp16* __restrict__ qh, fp16* __restrict__ kh,
             fp16* __restrict__ vth,
             int M, int N, int K)
{
    extern __shared__ __align__(16) char sm[];
    const uint32_t sb = smem_u32(sm);
    const int tid = threadIdx.x;
    const int wid = tid >> 5, lane = tid & 31;
    const int g = lane >> 2, tg = lane & 3;
    const int m0 = blockIdx.y * GBM, n0 = blockIdx.x * GBN;
    const int m0w = (wid >> 2) * 64, n0w = (wid & 3) * 32;

    float acc[4][4][4];
#pragma unroll
    for (int i = 0; i < 4; i++)
#pragma unroll
        for (int j = 0; j < 4; j++)
#pragma unroll
            for (int e = 0; e < 4; e++) acc[i][j][e] = 0.0f;

    auto load_stage = [&](int c) {
        const int kt = c * GBK;
        const uint32_t so = (uint32_t)(c % 3) * GSTAGE;
#pragma unroll
        for (int i = 0; i < 2; i++) {                 // A hi: 512 16B chunks
            int ci = tid + i * 256;
            int row = ci >> 2, kc = ci & 3;
            cpa16(sb + so + (uint32_t)(row * 80 + kc * 16),
                  Ah + (size_t)(m0 + row) * K + kt + kc * 8);
        }
#pragma unroll
        for (int i = 0; i < 2; i++) {                 // B hi: 512 16B chunks
            int ci = tid + i * 256;
            int row = ci >> 2, kc = ci & 3;
            cpa16(sb + so + GB_OFF + (uint32_t)(row * 80 + kc * 16),
                  Bh + (size_t)(n0 + row) * K + kt + kc * 8);
        }
        cp_commit();
    };

    auto compute = [&](int c) {
        const uint32_t so = (uint32_t)(c % 3) * GSTAGE;
#pragma unroll
        for (int ks = 0; ks < 2; ks++) {
            const uint32_t kb = (uint32_t)(ks * 32);
            uint32_t aH[4][4];
#pragma unroll
            for (int mf = 0; mf < 4; mf++) {
                uint32_t ad = sb + so +
                    (uint32_t)((m0w + mf * 16 + (lane & 15)) * 80) +
                    kb + (uint32_t)((lane >> 4) * 16);
                ldm_x4(aH[mf], ad);
            }
#pragma unroll
            for (int nf = 0; nf < 4; nf++) {
                uint32_t bd = sb + so + GB_OFF +
                    (uint32_t)((n0w + nf * 8 + (lane & 7)) * 80) +
                    kb + (uint32_t)(((lane >> 3) & 1) * 16);
                uint32_t bH[2];
                ldm_x2(bH, bd);
#pragma unroll
                for (int mf = 0; mf < 4; mf++)
                    mmaf32(acc[mf][nf], aH[mf], bH);
            }
        }
    };

    const int NC = K / GBK;
    load_stage(0);
    load_stage(1);
    for (int c = 0; c < NC; c++) {
        if (c == NC - 1) cp_wait<0>(); else cp_wait<1>();
        __syncthreads();
        if (c + 2 < NC) load_stage(c + 2);
        compute(c);
    }

    // ---- epilogue ----
#pragma unroll
    for (int mf = 0; mf < 4; mf++) {
        const int r = m0 + m0w + mf * 16 + g;
#pragma unroll
        for (int nf = 0; nf < 4; nf++) {
            const int col = n0 + n0w + nf * 8 + tg * 2;
            const float b0 = bias[col], b1 = bias[col + 1];
#pragma unroll
            for (int half = 0; half < 2; half++) {
                const int rr = r + half * 8;
                const float v0 = acc[mf][nf][half * 2 + 0] + b0;
                const float v1 = acc[mf][nf][half * 2 + 1] + b1;
                if (MODE == 0) {
                    *(float2*)(C + (size_t)rr * N + col) = make_float2(v0, v1);
                } else {
                    if (col < 1024) {                 // Q: hi only
                        *(uint32_t*)(qh + (size_t)rr * EMB + col) = packh(v0, v1);
                    } else if (col < 2048) {          // K: hi only
                        *(uint32_t*)(kh + (size_t)rr * EMB + (col - 1024)) =
                            packh(v0, v1);
                    } else {                          // V: transposed, hi only
                        const int d = col - 2048;
                        const int hh = d >> 6, dd = d & 63;
                        const int bb = rr >> 11, rs = rr & 2047;
                        const size_t vb =
                            ((size_t)(bb * NH + hh) * HD + dd) * SEQ + rs;
                        vth[vb]       = __float2half_rn(v0);
                        vth[vb + SEQ] = __float2half_rn(v1);
                    }
                }
            }
        }
    }
}

// ---------------------------------------------------------------------------
// Flash attention: QK 1-term (Qh vs Kh), PV 1-term (Ph vs Vh).
// CTA = 128 q rows x (b,h); 8 warps x 16 q rows; KV tiles of 128, double-buffered.
// smem: Q 18.4KB + 2 KV stages (35.8KB each) = 90KB.
// ---------------------------------------------------------------------------
#define AKV0    18432u
#define AKV_V   18432u   // within stage
#define AKVSTG  35840u
#define ATT_SMEM (AKV0 + 2u * AKVSTG)   // 90112 bytes

__global__ __launch_bounds__(256, 1)
void attention_mma(const fp16* __restrict__ qh,
                   const fp16* __restrict__ kh, const fp16* __restrict__ vth,
                   fp16* __restrict__ ath,
                   const int* __restrict__ causal_flag)
{
    extern __shared__ __align__(16) char sm[];
    const uint32_t sb = smem_u32(sm);
    const int tid = threadIdx.x, wid = tid >> 5, lane = tid & 31;
    const int g = lane >> 2, tg = lane & 3;
    const int qt = (SEQ / 128 - 1) - blockIdx.x;   // long CTAs first
    const int bh = blockIdx.y, b = bh / NH, h = bh % NH;
    const int causal = *causal_flag;
    const int q0 = qt * 128;

    auto load_kv = [&](int kvt, int st) {
        const int kv0 = kvt * 128;
        const uint32_t so = AKV0 + (uint32_t)st * AKVSTG;
#pragma unroll
        for (int i = 0; i < 4; i++) {            // K hi: 1024 chunks
            int ci = tid + i * 256;
            int row = ci >> 3, kc = ci & 7;
            const fp16* src = kh + (size_t)(b * SEQ + kv0 + row) * EMB +
                              h * HD + kc * 8;
            cpa16(sb + so + (uint32_t)(row * 144 + kc * 16), src);
        }
#pragma unroll
        for (int i = 0; i < 4; i++) {            // V hi: 1024 chunks
            int ci = tid + i * 256;
            int row = ci >> 4, kc = ci & 15;
            const fp16* src = vth + ((size_t)bh * HD + row) * SEQ + kv0 + kc * 8;
            cpa16(sb + so + AKV_V + (uint32_t)(row * 272 + kc * 16), src);
        }
        cp_commit();
    };

    // ---- prologue: Q hi + KV(0) ----
#pragma unroll
    for (int i = 0; i < 4; i++) {
        int ci = tid + i * 256;
        int row = ci >> 3, kc = ci & 7;
        const fp16* src = qh + (size_t)(b * SEQ + q0 + row) * EMB +
                          h * HD + kc * 8;
        cpa16(sb + (uint32_t)(row * 144 + kc * 16), src);
    }
    load_kv(0, 0);

    float o[8][4];
#pragma unroll
    for (int i = 0; i < 8; i++)
#pragma unroll
        for (int e = 0; e < 4; e++) o[i][e] = 0.0f;
    float m0v = -1e30f, m1v = -1e30f, l0v = 0.0f, l1v = 0.0f;

    const int nkv = causal ? (qt + 1) : (SEQ / 128);
    for (int kvt = 0; kvt < nkv; kvt++) {
        cp_wait<0>();
        __syncthreads();
        if (kvt + 1 < nkv) load_kv(kvt + 1, (kvt + 1) & 1);  // overlaps compute

        const uint32_t kvb = AKV0 + (uint32_t)(kvt & 1) * AKVSTG;

        // ---- S = Qh @ Kh^T ----
        float s[16][4];
#pragma unroll
        for (int nf = 0; nf < 16; nf++)
#pragma unroll
            for (int e = 0; e < 4; e++) s[nf][e] = 0.0f;

#pragma unroll
        for (int ks = 0; ks < 4; ks++) {
            const uint32_t kb = (uint32_t)(ks * 32);
            uint32_t aH[4];
            uint32_t ad = sb + (uint32_t)((wid * 16 + (lane & 15)) * 144) +
                          kb + (uint32_t)((lane >> 4) * 16);
            ldm_x4(aH, ad);
#pragma unroll
            for (int nf = 0; nf < 16; nf++) {
                uint32_t bd = sb + kvb +
                    (uint32_t)((nf * 8 + (lane & 7)) * 144) +
                    kb + (uint32_t)(((lane >> 3) & 1) * 16);
                uint32_t bH[2];
                ldm_x2(bH, bd);
                mmaf32(s[nf], aH, bH);
            }
        }

        // ---- scale + causal mask (diagonal tile only) ----
        const bool dm = (causal != 0) && (kvt == qt);
#pragma unroll
        for (int nf = 0; nf < 16; nf++) {
#pragma unroll
            for (int e = 0; e < 4; e++) {
                float v = s[nf][e] * 0.125f;   // 1/sqrt(64)
                if (dm) {
                    int qr = wid * 16 + g + ((e >= 2) ? 8 : 0);
                    int kc = nf * 8 + tg * 2 + (e & 1);
                    if (kc > qr) v = -1e30f;
                }
                s[nf][e] = v;
            }
        }

        // ---- online softmax (rows g and g+8) ----
        float mx0 = -1e30f, mx1 = -1e30f;
#pragma unroll
        for (int nf = 0; nf < 16; nf++) {
            mx0 = fmaxf(mx0, fmaxf(s[nf][0], s[nf][1]));
            mx1 = fmaxf(mx1, fmaxf(s[nf][2], s[nf][3]));
        }
        mx0 = fmaxf(mx0, __shfl_xor_sync(0xffffffffu, mx0, 1));
        mx0 = fmaxf(mx0, __shfl_xor_sync(0xffffffffu, mx0, 2));
        mx1 = fmaxf(mx1, __shfl_xor_sync(0xffffffffu, mx1, 1));
        mx1 = fmaxf(mx1, __shfl_xor_sync(0xffffffffu, mx1, 2));

        const float mn0 = fmaxf(m0v, mx0), mn1 = fmaxf(m1v, mx1);
        const float al0 = __expf(m0v - mn0), al1 = __expf(m1v - mn1);
        m0v = mn0; m1v = mn1;

        float rs0 = 0.0f, rs1 = 0.0f;
#pragma unroll
        for (int nf = 0; nf < 16; nf++) {
            s[nf][0] = __expf(s[nf][0] - mn0); rs0 += s[nf][0];
            s[nf][1] = __expf(s[nf][1] - mn0); rs0 += s[nf][1];
            s[nf][2] = __expf(s[nf][2] - mn1); rs1 += s[nf][2];
            s[nf][3] = __expf(s[nf][3] - mn1); rs1 += s[nf][3];
        }
        rs0 += __shfl_xor_sync(0xffffffffu, rs0, 1);
        rs0 += __shfl_xor_sync(0xffffffffu, rs0, 2);
        rs1 += __shfl_xor_sync(0xffffffffu, rs1, 1);
        rs1 += __shfl_xor_sync(0xffffffffu, rs1, 2);
        l0v = l0v * al0 + rs0;
        l1v = l1v * al1 + rs1;

#pragma unroll
        for (int nf = 0; nf < 8; nf++) {
            o[nf][0] *= al0; o[nf][1] *= al0;
            o[nf][2] *= al1; o[nf][3] *= al1;
        }

        // ---- O += Ph @ Vh (1-term P; V^T frags via ldmatrix) ----
#pragma unroll
        for (int kf = 0; kf < 8; kf++) {
            uint32_t aH[4];
            aH[0] = packh(s[2 * kf][0],     s[2 * kf][1]);
            aH[1] = packh(s[2 * kf][2],     s[2 * kf][3]);
            aH[2] = packh(s[2 * kf + 1][0], s[2 * kf + 1][1]);
            aH[3] = packh(s[2 * kf + 1][2], s[2 * kf + 1][3]);
#pragma unroll
            for (int nf = 0; nf < 8; nf++) {
                uint32_t vd = sb + kvb + AKV_V +
                    (uint32_t)((nf * 8 + (lane & 7)) * 272) +
                    (uint32_t)(kf * 32) + (uint32_t)(((lane >> 3) & 1) * 16);
                uint32_t bH[2];
                ldm_x2(bH, vd);
                mmaf32(o[nf], aH, bH);
            }
        }
        __syncthreads();   // all warps done with stage before next overwrite
    }

    // ---- normalize + write hi fp16 plane of O ----
    const float inv0 = 1.0f / l0v, inv1 = 1.0f / l1v;
    const size_t r0 = (size_t)(b * SEQ + q0 + wid * 16 + g);
#pragma unroll
    for (int nf = 0; nf < 8; nf++) {
        const int col = h * HD + nf * 8 + tg * 2;
        *(uint32_t*)(ath + r0 * EMB + col) =
            packh(o[nf][0] * inv0, o[nf][1] * inv0);
        *(uint32_t*)(ath + (r0 + 8) * EMB + col) =
            packh(o[nf][2] * inv1, o[nf][3] * inv1);
    }
}

// ---------------------------------------------------------------------------
extern "C" void kernel_launch(void* const* d_in, const int* in_sizes, int n_in,
                              void* d_out, int out_size)
{
    (void)in_sizes; (void)n_in; (void)out_size;
    const float* x      = (const float*)d_in[0];
    const float* w_qkv  = (const float*)d_in[1];
    const float* b_qkv  = (const float*)d_in[2];
    const float* w_out  = (const float*)d_in[3];
    const float* b_out  = (const float*)d_in[4];
    const int*   causal = (const int*)d_in[5];
    float* out = (float*)d_out;

    fp16 *xh, *wqh, *woh, *qh, *kh, *vth, *ath;
    cudaGetSymbolAddress((void**)&xh,  g_xh);
    cudaGetSymbolAddress((void**)&wqh, g_wqh);  cudaGetSymbolAddress((void**)&woh, g_woh);
    cudaGetSymbolAddress((void**)&qh,  g_qh);
    cudaGetSymbolAddress((void**)&kh,  g_kh);   cudaGetSymbolAddress((void**)&vth, g_vth);
    cudaGetSymbolAddress((void**)&ath, g_ath);

    cudaFuncSetAttribute(gemm_1t<0>, cudaFuncAttributeMaxDynamicSharedMemorySize,
                         (int)GEMM_SMEM);
    cudaFuncSetAttribute(gemm_1t<1>, cudaFuncAttributeMaxDynamicSharedMemorySize,
                         (int)GEMM_SMEM);
    cudaFuncSetAttribute(attention_mma, cudaFuncAttributeMaxDynamicSharedMemorySize,
                         (int)ATT_SMEM);

    // 1) pre-convert: all inputs -> fp16 hi planes
    convert_hi<<<(MTOT * EMB / 4 + 255) / 256, 256>>>(
        (const float4*)x, (uint2*)xh, MTOT * EMB / 4);
    convert_hi<<<(NQKV * EMB / 4 + 255) / 256, 256>>>(
        (const float4*)w_qkv, (uint2*)wqh, NQKV * EMB / 4);
    convert_hi<<<(EMB * EMB / 4 + 255) / 256, 256>>>(
        (const float4*)w_out, (uint2*)woh, EMB * EMB / 4);

    // 2) QKV projection (1-term) -> Q hi, K hi, V^T hi
    gemm_1t<1><<<dim3(NQKV / GBN, MTOT / GBM), 256, GEMM_SMEM>>>(
        xh, wqh, b_qkv, nullptr, qh, kh, vth, MTOT, NQKV, EMB);

    // 3) causal flash attention -> O hi plane
    attention_mma<<<dim3(SEQ / 128, BATCH * NH), 256, ATT_SMEM>>>(
        qh, kh, vth, ath, causal);

    // 4) output projection (1-term) -> fp32 out
    gemm_1t<0><<<dim3(EMB / GBN, MTOT / GBM), 256, GEMM_SMEM>>>(
        ath, woh, b_out, out, nullptr, nullptr, nullptr,
        MTOT, EMB, EMB);
}